// round 12
// baseline (speedup 1.0000x reference)
#include <cuda_runtime.h>
#include <math.h>

#define N 3072
#define F 128
#define E 24576
#define TWOE 49152
#define NNW (N * N / 32)   // dedup bitmap words
#define STRIDE 96          // CSR slots per destination node (indeg ~Poisson(16))
#define CSTRIDE 32         // contraction out-adjacency slots (outdeg ~Poisson(8))

// ---------------- static scratch ----------------
__device__ float          g_a[N];
__device__ float          g_c[N];
__device__ unsigned       g_bitmap[NNW];        // dedup of directed pairs (1.18 MB)
__device__ int            g_cnt[N];             // per-destination CSR cursor == indeg
__device__ int            g_srci[N * STRIDE];   // CSR: source node per slot
__device__ float          g_wv[N * STRIDE];     // CSR: weight per slot
__device__ int            g_ccnt[N];            // contraction out-degree
__device__ unsigned short g_cadj[N * CSTRIDE];  // p-major out-neighbors (u16, 196KB -> L1)
__device__ int            g_deg[N];             // incident-to-contraction flag
__device__ int            g_cluster[N];
__device__ float          g_y[N * F];           // per-node gathered features

// ---------------- kernels ----------------

// big output zero (39 MB, poisoned by harness) — side stream
__global__ void k_zero_out(float* out, long long n) {
    long long i = (long long)blockIdx.x * blockDim.x + threadIdx.x;
    long long s = (long long)gridDim.x * blockDim.x;
    long long n4 = n >> 2;
    float4* p4 = (float4*)out;
    float4 z = make_float4(0.f, 0.f, 0.f, 0.f);
    for (long long j = i; j < n4; j += s) p4[j] = z;
    for (long long j = (n4 << 2) + i; j < n; j += s) out[j] = 0.0f;
}

// per-node dots + scratch zeroing
__global__ void k_dots(const float* __restrict__ x, const float* __restrict__ w) {
    int i = blockIdx.x, t = threadIdx.x;
    if (t < 24) ((uint4*)g_bitmap)[i * 24 + t] = make_uint4(0u, 0u, 0u, 0u);
    if (t == 32) g_cnt[i] = 0;
    if (t == 33) g_deg[i] = 0;
    if (t == 34) g_ccnt[i] = 0;

    float xv = x[i * F + t];
    float pa = xv * w[t];
    float pc = xv * w[F + t];
    #pragma unroll
    for (int o = 16; o; o >>= 1) {
        pa += __shfl_down_sync(0xffffffffu, pa, o);
        pc += __shfl_down_sync(0xffffffffu, pc, o);
    }
    __shared__ float sa[4], sc[4];
    if ((t & 31) == 0) { sa[t >> 5] = pa; sc[t >> 5] = pc; }
    __syncthreads();
    if (t == 0) {
        g_a[i] = sa[0] + sa[1] + sa[2] + sa[3];
        g_c[i] = sc[0] + sc[1] + sc[2] + sc[3];
    }
}

// per input edge, both directions: dedup-claim, score, CSR + p-major contraction adj
__global__ void k_edges(const int* __restrict__ ei, const float* __restrict__ bptr) {
    int k = blockIdx.x * blockDim.x + threadIdx.x;   // grid covers exactly E
    int u = ei[k], v = ei[E + k];
    bool valid = (u != v);
    float b = *bptr;
    #pragma unroll
    for (int d = 0; d < 2; d++) {
        int p = d ? v : u;
        int q = d ? u : v;
        float e = 0.0f;
        bool win = false;
        if (valid) {
            e = tanhf(g_a[p] + g_c[q] + b);
            if (e > 0.0f) { g_deg[p] = 1; g_deg[q] = 1; }
            unsigned idx = (unsigned)p * N + (unsigned)q;
            unsigned bit = 1u << (idx & 31u);
            unsigned old = atomicOr(&g_bitmap[idx >> 5], bit);
            win = !(old & bit);
        }
        if (win) {   // first claimer of this ordered pair
            int pos = atomicAdd(&g_cnt[q], 1);
            if (pos < STRIDE) {
                g_srci[q * STRIDE + pos] = p;
                g_wv[q * STRIDE + pos] = e;
            }
            if (e > 0.0f) {  // contraction out-edge p -> q, p-major slot
                int cp = atomicAdd(&g_ccnt[p], 1);
                if (cp < CSTRIDE) g_cadj[p * CSTRIDE + cp] = (unsigned short)q;
            }
        }
    }
}

// single block, 1024 threads: owner-centric min-label CC.
// int labels in shared; lab[p] register-held per owned node; adjacency u16 in
// global (L1-resident), vectorized uint4 loads -> ONE random LDS per edge.
// One sweep + full path compression per round.
__global__ void __launch_bounds__(1024) k_cc() {
    __shared__ int lab[N];
    __shared__ int cum[N];
    __shared__ int wsum[32];
    __shared__ int changed;
    int t = threadIdx.x;
    int lane = t & 31, wid = t >> 5;
    int n0 = t * 3;

    lab[n0] = n0; lab[n0 + 1] = n0 + 1; lab[n0 + 2] = n0 + 2;
    int c0 = min(g_ccnt[n0], CSTRIDE);
    int c1 = min(g_ccnt[n0 + 1], CSTRIDE);
    int c2 = min(g_ccnt[n0 + 2], CSTRIDE);
    __syncthreads();

    for (;;) {
        if (t == 0) changed = 0;
        __syncthreads();
        // owner sweep: lab[i] in register; neighbors via vectorized u16 loads
        #pragma unroll
        for (int r = 0; r < 3; r++) {
            int i = n0 + r;
            int cnt = (r == 0) ? c0 : (r == 1) ? c1 : c2;
            const unsigned short* __restrict__ adj = &g_cadj[i * CSTRIDE];
            int Li = lab[i];
            int lm = lab[Li];
            if (lm < Li) Li = lm;
            int j = 0;
            for (; j + 8 <= cnt; j += 8) {
                uint4 pk = *(const uint4*)(adj + j);        // 8 u16 neighbors
                int q0 = pk.x & 0xFFFF, q1 = pk.x >> 16;
                int q2 = pk.y & 0xFFFF, q3 = pk.y >> 16;
                int q4 = pk.z & 0xFFFF, q5 = pk.z >> 16;
                int q6 = pk.w & 0xFFFF, q7 = pk.w >> 16;
                int l0 = lab[q0], l1 = lab[q1], l2 = lab[q2], l3 = lab[q3];
                int l4 = lab[q4], l5 = lab[q5], l6 = lab[q6], l7 = lab[q7];
                Li = min(Li, min(min(min(l0, l1), min(l2, l3)),
                                 min(min(l4, l5), min(l6, l7))));
            }
            for (; j < cnt; j++) Li = min(Li, lab[adj[j]]);
            if (Li < lab[i]) { lab[i] = Li; changed = 1; }
        }
        __syncthreads();
        // full path compression to root (owner-write only)
        #pragma unroll
        for (int r = 0; r < 3; r++) {
            int i = n0 + r;
            int l = lab[i];
            int m = lab[l];
            while (m != l) { l = m; m = lab[l]; }
            if (l < lab[i]) { lab[i] = l; changed = 1; }
        }
        __syncthreads();
        if (!changed) break;
        __syncthreads();
    }

    // ---- rank roots -> consecutive ids (warp shfl scans) ----
    int f0 = (lab[n0]     == n0)     ? 1 : 0;
    int f1 = (lab[n0 + 1] == n0 + 1) ? 1 : 0;
    int f2 = (lab[n0 + 2] == n0 + 2) ? 1 : 0;
    int s3 = f0 + f1 + f2;
    int inc = s3;
    #pragma unroll
    for (int off = 1; off < 32; off <<= 1) {
        int nv = __shfl_up_sync(0xffffffffu, inc, off);
        if (lane >= off) inc += nv;
    }
    if (lane == 31) wsum[wid] = inc;
    __syncthreads();
    if (wid == 0) {
        int vi = wsum[lane];
        #pragma unroll
        for (int off = 1; off < 32; off <<= 1) {
            int nv = __shfl_up_sync(0xffffffffu, vi, off);
            if (lane >= off) vi += nv;
        }
        wsum[lane] = vi;
    }
    __syncthreads();
    int wexcl = (wid == 0) ? 0 : wsum[wid - 1];
    int excl = wexcl + inc - s3;
    cum[n0]     = excl + f0;
    cum[n0 + 1] = excl + f0 + f1;
    cum[n0 + 2] = excl + f0 + f1 + f2;
    __syncthreads();
    g_cluster[n0]     = cum[lab[n0]] - 1;
    g_cluster[n0 + 1] = cum[lab[n0 + 1]] - 1;
    g_cluster[n0 + 2] = cum[lab[n0 + 2]] - 1;
}

// per-node feature gather (cluster-independent) — overlaps k_cc on side stream
__global__ void k_acc(const float* __restrict__ x) {
    int v = blockIdx.x, t = threadIdx.x;
    __shared__ int su[STRIDE];
    __shared__ float sw[STRIDE];
    int deg = g_cnt[v];
    if (deg > STRIDE) deg = STRIDE;
    if (t < deg) { su[t] = g_srci[v * STRIDE + t]; sw[t] = g_wv[v * STRIDE + t]; }
    __syncthreads();
    float acc = 0.0f;
    for (int i = 0; i < deg; i++)
        acc += sw[i] * __ldg(&x[su[i] * F + t]);
    if (g_deg[v] == 0) acc += x[v * F + t];
    g_y[v * F + t] = acc;
}

// final scatter: X_new by cluster, A counts, cluster output
__global__ void k_fin(float* __restrict__ Xout, float* __restrict__ Aout,
                      float* __restrict__ Cout) {
    int v = blockIdx.x, t = threadIdx.x;
    int cv = g_cluster[v];
    atomicAdd(&Xout[cv * F + t], g_y[v * F + t]);
    int deg = g_cnt[v];
    if (deg > STRIDE) deg = STRIDE;
    if (t < deg) {
        int p = g_cluster[g_srci[v * STRIDE + t]];
        if (p != cv) atomicAdd(&Aout[(long long)p * N + cv], 1.0f);
    }
    if (t == 0) Cout[v] = (float)cv;
}

// ---------------- launcher ----------------
extern "C" void kernel_launch(void* const* d_in, const int* in_sizes, int n_in,
                              void* d_out, int out_size) {
    const float* x  = (const float*)d_in[0];
    const int*   ei = (const int*)d_in[1];
    // d_in[2] = batch (all zeros, unused)
    const float* w  = (const float*)d_in[3];
    const float* b  = (const float*)d_in[4];

    float* out  = (float*)d_out;
    float* Xout = out;                        // [N, F]
    float* Aout = out + (long long)N * F;     // [N, N]
    float* Bout = Aout + (long long)N * N;    // [N] zeros (k_zero_out)
    float* Cout = Bout + N;                   // [N]
    (void)Bout;

    static cudaStream_t s2 = (cudaStream_t)0;
    static cudaEvent_t evA = nullptr, evE = nullptr, evB = nullptr;
    static bool inited = false;
    if (!inited) {
        inited = true;
        if (cudaStreamCreateWithFlags(&s2, cudaStreamNonBlocking) != cudaSuccess)
            s2 = (cudaStream_t)0;
        cudaEventCreateWithFlags(&evA, cudaEventDisableTiming);
        cudaEventCreateWithFlags(&evE, cudaEventDisableTiming);
        cudaEventCreateWithFlags(&evB, cudaEventDisableTiming);
    }

    // fork side stream: zero output while main stream computes dots/edges
    cudaEventRecord(evA, 0);
    cudaStreamWaitEvent(s2, evA, 0);
    k_zero_out<<<1024, 256, 0, s2>>>(out, (long long)out_size);

    k_dots<<<N, F>>>(x, w);
    k_edges<<<E / 128, 128>>>(ei, b);
    cudaEventRecord(evE, 0);

    // side stream: feature gather overlaps single-SM k_cc
    cudaStreamWaitEvent(s2, evE, 0);
    k_acc<<<N, F, 0, s2>>>(x);
    cudaEventRecord(evB, s2);

    k_cc<<<1, 1024>>>();

    // join, then final scatter
    cudaStreamWaitEvent(0, evB, 0);
    k_fin<<<N, F>>>(Xout, Aout, Cout);
}

// round 13
// speedup vs baseline: 1.2405x; 1.2405x over previous
#include <cuda_runtime.h>
#include <math.h>

#define N 3072
#define F 128
#define E 24576
#define TWOE 49152
#define NNW (N * N / 32)   // dedup bitmap words
#define STRIDE 96          // CSR slots per destination node (indeg ~Poisson(16))

// ---------------- static scratch ----------------
__device__ float    g_a[N];
__device__ float    g_c[N];
__device__ unsigned g_bitmap[NNW];        // dedup of directed pairs (1.18 MB)
__device__ int      g_cpq[TWOE];          // deduped contraction edges (e>0), packed (p<<16)|q
__device__ int      g_cpq2[TWOE];         // ping-pong buffer for active-edge compaction
__device__ int      g_ncedges;
__device__ int      g_cnt[N];             // per-destination CSR cursor == indeg
__device__ int      g_srci[N * STRIDE];   // CSR: source node per slot
__device__ float    g_wv[N * STRIDE];     // CSR: weight per slot
__device__ int      g_deg[N];             // incident-to-contraction flag
__device__ int      g_cluster[N];
__device__ float    g_y[N * F];           // per-node gathered features

// ---------------- kernels ----------------

// big output zero (39 MB, poisoned by harness) — side stream
__global__ void k_zero_out(float* out, long long n) {
    long long i = (long long)blockIdx.x * blockDim.x + threadIdx.x;
    long long s = (long long)gridDim.x * blockDim.x;
    long long n4 = n >> 2;
    float4* p4 = (float4*)out;
    float4 z = make_float4(0.f, 0.f, 0.f, 0.f);
    for (long long j = i; j < n4; j += s) p4[j] = z;
    for (long long j = (n4 << 2) + i; j < n; j += s) out[j] = 0.0f;
}

// per-node dots + scratch zeroing
__global__ void k_dots(const float* __restrict__ x, const float* __restrict__ w) {
    int i = blockIdx.x, t = threadIdx.x;
    if (t < 24) ((uint4*)g_bitmap)[i * 24 + t] = make_uint4(0u, 0u, 0u, 0u);
    if (t == 32) g_cnt[i] = 0;
    if (t == 33) g_deg[i] = 0;
    if (i == 0 && t == 34) g_ncedges = 0;

    float xv = x[i * F + t];
    float pa = xv * w[t];
    float pc = xv * w[F + t];
    #pragma unroll
    for (int o = 16; o; o >>= 1) {
        pa += __shfl_down_sync(0xffffffffu, pa, o);
        pc += __shfl_down_sync(0xffffffffu, pc, o);
    }
    __shared__ float sa[4], sc[4];
    if ((t & 31) == 0) { sa[t >> 5] = pa; sc[t >> 5] = pc; }
    __syncthreads();
    if (t == 0) {
        g_a[i] = sa[0] + sa[1] + sa[2] + sa[3];
        g_c[i] = sc[0] + sc[1] + sc[2] + sc[3];
    }
}

// per input edge, both directions: dedup-claim, score, CSR + contraction list
__global__ void k_edges(const int* __restrict__ ei, const float* __restrict__ bptr) {
    int k = blockIdx.x * blockDim.x + threadIdx.x;   // grid covers exactly E
    int u = ei[k], v = ei[E + k];
    bool valid = (u != v);
    float b = *bptr;
    int lane = threadIdx.x & 31;
    unsigned lt = (1u << lane) - 1u;
    #pragma unroll
    for (int d = 0; d < 2; d++) {
        int p = d ? v : u;
        int q = d ? u : v;
        float e = 0.0f;
        bool win = false;
        if (valid) {
            e = tanhf(g_a[p] + g_c[q] + b);
            if (e > 0.0f) { g_deg[p] = 1; g_deg[q] = 1; }
            unsigned idx = (unsigned)p * N + (unsigned)q;
            unsigned bit = 1u << (idx & 31u);
            unsigned old = atomicOr(&g_bitmap[idx >> 5], bit);
            win = !(old & bit);
        }
        if (win) {   // first claimer: CSR slot at destination q
            int pos = atomicAdd(&g_cnt[q], 1);
            if (pos < STRIDE) {
                g_srci[q * STRIDE + pos] = p;
                g_wv[q * STRIDE + pos] = e;
            }
        }
        // warp-aggregated append to contraction edge list
        bool cwin = win && (e > 0.0f);
        unsigned cm = __ballot_sync(0xffffffffu, cwin);
        if (cm) {
            int leader = __ffs(cm) - 1;
            int base;
            if (lane == leader) base = atomicAdd(&g_ncedges, __popc(cm));
            base = __shfl_sync(0xffffffffu, base, leader);
            if (cwin) g_cpq[base + __popc(cm & lt)] = (p << 16) | q;
        }
    }
}

// single block, 1024 threads: edge-centric min-label CC with monotone pruning.
// Edges whose lab[q]==0 can never fire again (labels only decrease; 0 is the
// global min and forces lab[p]=0 immediately) -> compact survivors each round.
__global__ void __launch_bounds__(1024) k_cc() {
    __shared__ int lab[N];
    __shared__ int cum[N];
    __shared__ int wsum[32];
    __shared__ int changed;
    __shared__ int nact;
    int t = threadIdx.x;
    int lane = t & 31, wid = t >> 5;
    unsigned lt = (1u << lane) - 1u;

    for (int i = t; i < N; i += 1024) lab[i] = i;
    int M = g_ncedges;
    int* src = g_cpq;
    int* dst = g_cpq2;
    __syncthreads();

    for (;;) {
        if (t == 0) { changed = 0; nact = 0; }
        __syncthreads();
        // one chaotic edge sweep (batched x8 for MLP) + ballot-compaction of
        // surviving edges into dst
        for (int b0 = 0; b0 < M; b0 += 8 * 1024) {
            int pq[8];
            #pragma unroll
            for (int j = 0; j < 8; j++) {
                int k = b0 + j * 1024 + t;
                pq[j] = (k < M) ? src[k] : -1;
            }
            #pragma unroll
            for (int j = 0; j < 8; j++) {
                bool keep = false;
                if (pq[j] >= 0) {
                    int p = pq[j] >> 16, q = pq[j] & 0xFFFF;
                    int lq = lab[q];
                    if (lq < lab[p]) {
                        int old = atomicMin(&lab[p], lq);
                        if (old > lq) changed = 1;
                    }
                    keep = (lq != 0);
                }
                unsigned m = __ballot_sync(0xffffffffu, keep);
                if (m) {
                    int leader = __ffs(m) - 1;
                    int base;
                    if (lane == leader) base = atomicAdd(&nact, __popc(m));
                    base = __shfl_sync(0xffffffffu, base, leader);
                    if (keep) dst[base + __popc(m & lt)] = pq[j];
                }
            }
        }
        __syncthreads();
        // full path compression to root
        for (int i = t; i < N; i += 1024) {
            int l = lab[i];
            int m = lab[l];
            while (m != l) { l = m; m = lab[l]; }
            if (l < lab[i]) { lab[i] = l; changed = 1; }
        }
        __syncthreads();
        if (!changed) break;
        M = nact;                      // read before next-round reset barrier
        { int* tmp = src; src = dst; dst = tmp; }
        __syncthreads();
    }

    // ---- rank roots -> consecutive ids (warp shfl scans) ----
    int n0 = t * 3;
    int f0 = (lab[n0]     == n0)     ? 1 : 0;
    int f1 = (lab[n0 + 1] == n0 + 1) ? 1 : 0;
    int f2 = (lab[n0 + 2] == n0 + 2) ? 1 : 0;
    int s3 = f0 + f1 + f2;
    int inc = s3;
    #pragma unroll
    for (int off = 1; off < 32; off <<= 1) {
        int nv = __shfl_up_sync(0xffffffffu, inc, off);
        if (lane >= off) inc += nv;
    }
    if (lane == 31) wsum[wid] = inc;
    __syncthreads();
    if (wid == 0) {
        int vi = wsum[lane];
        #pragma unroll
        for (int off = 1; off < 32; off <<= 1) {
            int nv = __shfl_up_sync(0xffffffffu, vi, off);
            if (lane >= off) vi += nv;
        }
        wsum[lane] = vi;
    }
    __syncthreads();
    int wexcl = (wid == 0) ? 0 : wsum[wid - 1];
    int excl = wexcl + inc - s3;
    cum[n0]     = excl + f0;
    cum[n0 + 1] = excl + f0 + f1;
    cum[n0 + 2] = excl + f0 + f1 + f2;
    __syncthreads();
    g_cluster[n0]     = cum[lab[n0]] - 1;
    g_cluster[n0 + 1] = cum[lab[n0 + 1]] - 1;
    g_cluster[n0 + 2] = cum[lab[n0 + 2]] - 1;
}

// per-node feature gather (cluster-independent) — overlaps k_cc on side stream
__global__ void k_acc(const float* __restrict__ x) {
    int v = blockIdx.x, t = threadIdx.x;
    __shared__ int su[STRIDE];
    __shared__ float sw[STRIDE];
    int deg = g_cnt[v];
    if (deg > STRIDE) deg = STRIDE;
    if (t < deg) { su[t] = g_srci[v * STRIDE + t]; sw[t] = g_wv[v * STRIDE + t]; }
    __syncthreads();
    float acc = 0.0f;
    for (int i = 0; i < deg; i++)
        acc += sw[i] * __ldg(&x[su[i] * F + t]);
    if (g_deg[v] == 0) acc += x[v * F + t];
    g_y[v * F + t] = acc;
}

// final scatter: X_new by cluster, A counts, cluster output
__global__ void k_fin(float* __restrict__ Xout, float* __restrict__ Aout,
                      float* __restrict__ Cout) {
    int v = blockIdx.x, t = threadIdx.x;
    int cv = g_cluster[v];
    atomicAdd(&Xout[cv * F + t], g_y[v * F + t]);
    int deg = g_cnt[v];
    if (deg > STRIDE) deg = STRIDE;
    if (t < deg) {
        int p = g_cluster[g_srci[v * STRIDE + t]];
        if (p != cv) atomicAdd(&Aout[(long long)p * N + cv], 1.0f);
    }
    if (t == 0) Cout[v] = (float)cv;
}

// ---------------- launcher ----------------
extern "C" void kernel_launch(void* const* d_in, const int* in_sizes, int n_in,
                              void* d_out, int out_size) {
    const float* x  = (const float*)d_in[0];
    const int*   ei = (const int*)d_in[1];
    // d_in[2] = batch (all zeros, unused)
    const float* w  = (const float*)d_in[3];
    const float* b  = (const float*)d_in[4];

    float* out  = (float*)d_out;
    float* Xout = out;                        // [N, F]
    float* Aout = out + (long long)N * F;     // [N, N]
    float* Bout = Aout + (long long)N * N;    // [N] zeros (k_zero_out)
    float* Cout = Bout + N;                   // [N]
    (void)Bout;

    static cudaStream_t s2 = (cudaStream_t)0;
    static cudaEvent_t evA = nullptr, evE = nullptr, evB = nullptr;
    static bool inited = false;
    if (!inited) {
        inited = true;
        if (cudaStreamCreateWithFlags(&s2, cudaStreamNonBlocking) != cudaSuccess)
            s2 = (cudaStream_t)0;
        cudaEventCreateWithFlags(&evA, cudaEventDisableTiming);
        cudaEventCreateWithFlags(&evE, cudaEventDisableTiming);
        cudaEventCreateWithFlags(&evB, cudaEventDisableTiming);
    }

    // fork side stream: zero output while main stream computes dots/edges
    cudaEventRecord(evA, 0);
    cudaStreamWaitEvent(s2, evA, 0);
    k_zero_out<<<1024, 256, 0, s2>>>(out, (long long)out_size);

    k_dots<<<N, F>>>(x, w);
    k_edges<<<E / 128, 128>>>(ei, b);
    cudaEventRecord(evE, 0);

    // side stream: feature gather overlaps single-SM k_cc
    cudaStreamWaitEvent(s2, evE, 0);
    k_acc<<<N, F, 0, s2>>>(x);
    cudaEventRecord(evB, s2);

    k_cc<<<1, 1024>>>();

    // join, then final scatter
    cudaStreamWaitEvent(0, evB, 0);
    k_fin<<<N, F>>>(Xout, Aout, Cout);
}

// round 14
// speedup vs baseline: 1.4377x; 1.1590x over previous
#include <cuda_runtime.h>
#include <math.h>

#define N 3072
#define F 128
#define E 24576
#define TWOE 49152
#define NNW (N * N / 32)   // dedup bitmap words
#define STRIDE 96          // CSR slots per destination node (indeg ~Poisson(16))

// ---------------- static scratch ----------------
__device__ float    g_a[N];
__device__ float    g_c[N];
__device__ unsigned g_bitmap[NNW];        // dedup of directed pairs (1.18 MB)
__device__ int      g_cpq[TWOE];          // deduped contraction edges (e>0), packed (p<<16)|q
__device__ int      g_ncedges;
__device__ int      g_lab0[N];            // seed labels: min(i, out-neighbors) from k_edges
__device__ int      g_cnt[N];             // per-destination CSR cursor == indeg
__device__ int      g_srci[N * STRIDE];   // CSR: source node per slot
__device__ float    g_wv[N * STRIDE];     // CSR: weight per slot
__device__ int      g_deg[N];             // incident-to-contraction flag
__device__ int      g_cluster[N];
__device__ float    g_y[N * F];           // per-node gathered features

// ---------------- kernels ----------------

// big output zero (39 MB, poisoned by harness) — side stream
__global__ void k_zero_out(float* out, long long n) {
    long long i = (long long)blockIdx.x * blockDim.x + threadIdx.x;
    long long s = (long long)gridDim.x * blockDim.x;
    long long n4 = n >> 2;
    float4* p4 = (float4*)out;
    float4 z = make_float4(0.f, 0.f, 0.f, 0.f);
    for (long long j = i; j < n4; j += s) p4[j] = z;
    for (long long j = (n4 << 2) + i; j < n; j += s) out[j] = 0.0f;
}

// per-node dots + scratch zeroing
__global__ void k_dots(const float* __restrict__ x, const float* __restrict__ w) {
    int i = blockIdx.x, t = threadIdx.x;
    if (t < 24) ((uint4*)g_bitmap)[i * 24 + t] = make_uint4(0u, 0u, 0u, 0u);
    if (t == 32) g_cnt[i] = 0;
    if (t == 33) g_deg[i] = 0;
    if (t == 35) g_lab0[i] = i;
    if (i == 0 && t == 34) g_ncedges = 0;

    float xv = x[i * F + t];
    float pa = xv * w[t];
    float pc = xv * w[F + t];
    #pragma unroll
    for (int o = 16; o; o >>= 1) {
        pa += __shfl_down_sync(0xffffffffu, pa, o);
        pc += __shfl_down_sync(0xffffffffu, pc, o);
    }
    __shared__ float sa[4], sc[4];
    if ((t & 31) == 0) { sa[t >> 5] = pa; sc[t >> 5] = pc; }
    __syncthreads();
    if (t == 0) {
        g_a[i] = sa[0] + sa[1] + sa[2] + sa[3];
        g_c[i] = sc[0] + sc[1] + sc[2] + sc[3];
    }
}

// per input edge, both directions: dedup-claim, score, CSR + contraction list
// + free label pre-sweep (atomicMin g_lab0[p] <- q for positive edges)
__global__ void k_edges(const int* __restrict__ ei, const float* __restrict__ bptr) {
    int k = blockIdx.x * blockDim.x + threadIdx.x;   // grid covers exactly E
    int u = ei[k], v = ei[E + k];
    bool valid = (u != v);
    float b = *bptr;
    int lane = threadIdx.x & 31;
    unsigned lt = (1u << lane) - 1u;
    #pragma unroll
    for (int d = 0; d < 2; d++) {
        int p = d ? v : u;
        int q = d ? u : v;
        float e = 0.0f;
        bool win = false;
        if (valid) {
            e = tanhf(g_a[p] + g_c[q] + b);
            if (e > 0.0f) {
                g_deg[p] = 1; g_deg[q] = 1;
                if (q < p) atomicMin(&g_lab0[p], q);   // seed sweep (dups harmless)
            }
            unsigned idx = (unsigned)p * N + (unsigned)q;
            unsigned bit = 1u << (idx & 31u);
            unsigned old = atomicOr(&g_bitmap[idx >> 5], bit);
            win = !(old & bit);
        }
        if (win) {   // first claimer: CSR slot at destination q
            int pos = atomicAdd(&g_cnt[q], 1);
            if (pos < STRIDE) {
                g_srci[q * STRIDE + pos] = p;
                g_wv[q * STRIDE + pos] = e;
            }
        }
        // warp-aggregated append to contraction edge list
        bool cwin = win && (e > 0.0f);
        unsigned cm = __ballot_sync(0xffffffffu, cwin);
        if (cm) {
            int leader = __ffs(cm) - 1;
            int base;
            if (lane == leader) base = atomicAdd(&g_ncedges, __popc(cm));
            base = __shfl_sync(0xffffffffu, base, leader);
            if (cwin) g_cpq[base + __popc(cm & lt)] = (p << 16) | q;
        }
    }
}

// single block, 1024 threads: edge-centric min-label CC (edges L1-resident),
// one chaotic sweep + full path compression per round; seeded labels;
// 2 barriers/round via __syncthreads_or
__global__ void __launch_bounds__(1024) k_cc() {
    __shared__ int lab[N];
    __shared__ int cum[N];
    __shared__ int wsum[32];
    int t = threadIdx.x;
    int lane = t & 31, wid = t >> 5;

    for (int i = t; i < N; i += 1024) lab[i] = g_lab0[i];   // seeded (1 round saved)
    int M = g_ncedges;
    __syncthreads();

    int any;
    do {
        bool ch = false;
        // one chaotic edge sweep, batched x8 for MLP (L1-hit after round 1)
        for (int base = t; base < M; base += 8 * 1024) {
            int pq[8];
            #pragma unroll
            for (int j = 0; j < 8; j++) {
                int k = base + j * 1024;
                pq[j] = (k < M) ? g_cpq[k] : 0;       // (0,0) harmless
            }
            #pragma unroll
            for (int j = 0; j < 8; j++) {
                int p = pq[j] >> 16, q = pq[j] & 0xFFFF;
                int lq = lab[q];
                if (lq < lab[p]) {
                    int old = atomicMin(&lab[p], lq);
                    if (old > lq) ch = true;
                }
            }
        }
        __syncthreads();
        // full path compression to root
        for (int i = t; i < N; i += 1024) {
            int l = lab[i];
            int m = lab[l];
            while (m != l) { l = m; m = lab[l]; }
            if (l < lab[i]) { lab[i] = l; ch = true; }
        }
        any = __syncthreads_or(ch ? 1 : 0);   // barrier + convergence check fused
    } while (any);

    // ---- rank roots -> consecutive ids (warp shfl scans) ----
    int n0 = t * 3;
    int f0 = (lab[n0]     == n0)     ? 1 : 0;
    int f1 = (lab[n0 + 1] == n0 + 1) ? 1 : 0;
    int f2 = (lab[n0 + 2] == n0 + 2) ? 1 : 0;
    int s3 = f0 + f1 + f2;
    int inc = s3;
    #pragma unroll
    for (int off = 1; off < 32; off <<= 1) {
        int nv = __shfl_up_sync(0xffffffffu, inc, off);
        if (lane >= off) inc += nv;
    }
    if (lane == 31) wsum[wid] = inc;
    __syncthreads();
    if (wid == 0) {
        int vi = wsum[lane];
        #pragma unroll
        for (int off = 1; off < 32; off <<= 1) {
            int nv = __shfl_up_sync(0xffffffffu, vi, off);
            if (lane >= off) vi += nv;
        }
        wsum[lane] = vi;
    }
    __syncthreads();
    int wexcl = (wid == 0) ? 0 : wsum[wid - 1];
    int excl = wexcl + inc - s3;
    cum[n0]     = excl + f0;
    cum[n0 + 1] = excl + f0 + f1;
    cum[n0 + 2] = excl + f0 + f1 + f2;
    __syncthreads();
    g_cluster[n0]     = cum[lab[n0]] - 1;
    g_cluster[n0 + 1] = cum[lab[n0 + 1]] - 1;
    g_cluster[n0 + 2] = cum[lab[n0 + 2]] - 1;
}

// per-node feature gather (cluster-independent) — overlaps k_cc on side stream
__global__ void k_acc(const float* __restrict__ x) {
    int v = blockIdx.x, t = threadIdx.x;
    __shared__ int su[STRIDE];
    __shared__ float sw[STRIDE];
    int deg = g_cnt[v];
    if (deg > STRIDE) deg = STRIDE;
    if (t < deg) { su[t] = g_srci[v * STRIDE + t]; sw[t] = g_wv[v * STRIDE + t]; }
    __syncthreads();
    float acc = 0.0f;
    for (int i = 0; i < deg; i++)
        acc += sw[i] * __ldg(&x[su[i] * F + t]);
    if (g_deg[v] == 0) acc += x[v * F + t];
    g_y[v * F + t] = acc;
}

// final scatter: X_new by cluster, A counts, cluster output
__global__ void k_fin(float* __restrict__ Xout, float* __restrict__ Aout,
                      float* __restrict__ Cout) {
    int v = blockIdx.x, t = threadIdx.x;
    int cv = g_cluster[v];
    atomicAdd(&Xout[cv * F + t], g_y[v * F + t]);
    int deg = g_cnt[v];
    if (deg > STRIDE) deg = STRIDE;
    if (t < deg) {
        int p = g_cluster[g_srci[v * STRIDE + t]];
        if (p != cv) atomicAdd(&Aout[(long long)p * N + cv], 1.0f);
    }
    if (t == 0) Cout[v] = (float)cv;
}

// ---------------- launcher ----------------
extern "C" void kernel_launch(void* const* d_in, const int* in_sizes, int n_in,
                              void* d_out, int out_size) {
    const float* x  = (const float*)d_in[0];
    const int*   ei = (const int*)d_in[1];
    // d_in[2] = batch (all zeros, unused)
    const float* w  = (const float*)d_in[3];
    const float* b  = (const float*)d_in[4];

    float* out  = (float*)d_out;
    float* Xout = out;                        // [N, F]
    float* Aout = out + (long long)N * F;     // [N, N]
    float* Bout = Aout + (long long)N * N;    // [N] zeros (k_zero_out)
    float* Cout = Bout + N;                   // [N]
    (void)Bout;

    static cudaStream_t s2 = (cudaStream_t)0;
    static cudaEvent_t evA = nullptr, evE = nullptr, evB = nullptr;
    static bool inited = false;
    if (!inited) {
        inited = true;
        if (cudaStreamCreateWithFlags(&s2, cudaStreamNonBlocking) != cudaSuccess)
            s2 = (cudaStream_t)0;
        cudaEventCreateWithFlags(&evA, cudaEventDisableTiming);
        cudaEventCreateWithFlags(&evE, cudaEventDisableTiming);
        cudaEventCreateWithFlags(&evB, cudaEventDisableTiming);
    }

    // fork side stream: zero output while main stream computes dots/edges
    cudaEventRecord(evA, 0);
    cudaStreamWaitEvent(s2, evA, 0);
    k_zero_out<<<1024, 256, 0, s2>>>(out, (long long)out_size);

    k_dots<<<N, F>>>(x, w);
    k_edges<<<E / 128, 128>>>(ei, b);
    cudaEventRecord(evE, 0);

    // side stream: feature gather overlaps single-SM k_cc
    cudaStreamWaitEvent(s2, evE, 0);
    k_acc<<<N, F, 0, s2>>>(x);
    cudaEventRecord(evB, s2);

    k_cc<<<1, 1024>>>();

    // join, then final scatter
    cudaStreamWaitEvent(0, evB, 0);
    k_fin<<<N, F>>>(Xout, Aout, Cout);
}